// round 3
// baseline (speedup 1.0000x reference)
#include <cuda_runtime.h>
#include <math.h>

#define NBATCH 8
#define NSEG 8
#define CH 512
#define CBOT 128
#define BN_EPS 1e-5f

// ---------------- scratch (no allocations allowed) ----------------
__device__ float g_theta[NBATCH * CH * NSEG];  // [nb][c][s]
__device__ float g_gate [NBATCH * CH * NSEG];  // [nb][c][s]
__device__ float g_gk   [NBATCH * CH * 3];     // [nb][c][k]

// ---------------- kernel 1: theta = spatial mean ----------------
// one warp per (n, c); n = nb*8 + s
__global__ __launch_bounds__(256) void k_theta(const float* __restrict__ x) {
    int wid  = (blockIdx.x * blockDim.x + threadIdx.x) >> 5;
    int lane = threadIdx.x & 31;
    if (wid >= NBATCH * NSEG * CH) return;
    int n = wid >> 9;
    int c = wid & 511;
    const float4* p = (const float4*)(x + (((size_t)n * CH + c) << 10));
    float s = 0.f;
#pragma unroll
    for (int i = 0; i < 8; i++) {
        float4 v = __ldcs(p + lane + (i << 5));
        s += (v.x + v.y) + (v.z + v.w);
    }
#pragma unroll
    for (int o = 16; o; o >>= 1) s += __shfl_xor_sync(0xffffffffu, s, o);
    if (lane == 0) {
        int nb = n >> 3, seg = n & 7;
        g_theta[(nb * CH + c) * NSEG + seg] = s * (1.f / 1024.f);
    }
}

// ---------------- kernel 2: fused G + L branch ----------------
// grid: 8 blocks (one per nb), 1024 threads
__global__ __launch_bounds__(1024) void k_branch(
        const float* __restrict__ l_w1,
        const float* __restrict__ g_w1,
        const float* __restrict__ g_bn_gamma,
        const float* __restrict__ g_bn_beta,
        const float* __restrict__ g_bn_mean,
        const float* __restrict__ g_bn_var,
        const float* __restrict__ g_w2,
        const float* __restrict__ l_bn_gamma,
        const float* __restrict__ l_bn_beta,
        const float* __restrict__ l_bn_mean,
        const float* __restrict__ l_bn_var,
        const float* __restrict__ l_w2) {
    // th[r][c]: r = segment+1 (rows 0 and 9 zero pad). stride 520 floats
    // (520 % 32 == 8 -> rows on distinct bank offsets; 2080B row, 16B aligned)
    __shared__ __align__(16) float th[10][520];
    __shared__ __align__(16) float u_s[8][132];

    int nb = blockIdx.x;
    int t  = threadIdx.x;

    // stage theta[nb] : 512 channels x 8 segments
#pragma unroll
    for (int j = 0; j < 4; j++) {
        int o = (j << 10) | t;
        int c = o >> 3, s = o & 7;
        th[s + 1][c] = g_theta[(nb * CH + c) * NSEG + s];
    }
    if (t < 520) { th[0][t] = 0.f; th[9][t] = 0.f; }
    __syncthreads();

    // ---- G branch: threads 0..511 handle channel t ----
    if (t < 512) {
        float tv[8];
#pragma unroll
        for (int s = 0; s < 8; s++) tv[s] = th[s + 1][t];
        float tk0 = 0.f, tk1 = 0.f, tk2 = 0.f;
#pragma unroll
        for (int i = 0; i < 16; i++) {
            float a = 0.f;
#pragma unroll
            for (int s = 0; s < 8; s++) a += __ldg(&g_w1[i * 8 + s]) * tv[s];
            a = (a - __ldg(&g_bn_mean[i])) *
                rsqrtf(__ldg(&g_bn_var[i]) + BN_EPS) * __ldg(&g_bn_gamma[i]) +
                __ldg(&g_bn_beta[i]);
            a = fmaxf(a, 0.f);
            tk0 += __ldg(&g_w2[0 * 16 + i]) * a;
            tk1 += __ldg(&g_w2[1 * 16 + i]) * a;
            tk2 += __ldg(&g_w2[2 * 16 + i]) * a;
        }
        float m  = fmaxf(tk0, fmaxf(tk1, tk2));
        float e0 = expf(tk0 - m), e1 = expf(tk1 - m), e2 = expf(tk2 - m);
        float inv = 1.f / (e0 + e1 + e2);
        float* gk = g_gk + (nb * CH + t) * 3;
        gk[0] = e0 * inv; gk[1] = e1 * inv; gk[2] = e2 * inv;
    }

    // ---- L conv1 over all 512 channels: thread = (cb, s) ----
    {
        int cb = t >> 3, s = t & 7;
        const float4* wp = (const float4*)(l_w1 + (size_t)cb * (CH * 3));
        const float* rm = th[s];      // segment s-1
        const float* r0 = th[s + 1];  // segment s
        const float* rp = th[s + 2];  // segment s+1
        float acc = 0.f;
#pragma unroll 8
        for (int q = 0; q < 128; q++) {  // 4 channels per iter
            float4 wa = wp[3 * q + 0];
            float4 wb = wp[3 * q + 1];
            float4 wc = wp[3 * q + 2];
            float4 tm = *(const float4*)(rm + 4 * q);
            float4 t0 = *(const float4*)(r0 + 4 * q);
            float4 tp = *(const float4*)(rp + 4 * q);
            acc += wa.x * tm.x + wa.y * t0.x + wa.z * tp.x;
            acc += wa.w * tm.y + wb.x * t0.y + wb.y * tp.y;
            acc += wb.z * tm.z + wb.w * t0.z + wc.x * tp.z;
            acc += wc.y * tm.w + wc.z * t0.w + wc.w * tp.w;
        }
        acc = (acc - __ldg(&l_bn_mean[cb])) *
              rsqrtf(__ldg(&l_bn_var[cb]) + BN_EPS) * __ldg(&l_bn_gamma[cb]) +
              __ldg(&l_bn_beta[cb]);
        u_s[s][cb] = fmaxf(acc, 0.f);
    }
    __syncthreads();

    // ---- 1x1 conv + sigmoid -> gate ----
#pragma unroll
    for (int j = 0; j < 4; j++) {
        int o  = (j << 10) | t;
        int c  = o >> 3, ss = o & 7;
        const float4* wp = (const float4*)(l_w2 + (size_t)c * CBOT);
        const float4* uu = (const float4*)(&u_s[ss][0]);
        float acc = 0.f;
#pragma unroll 8
        for (int q = 0; q < 32; q++) {
            float4 w = wp[q], v = uu[q];
            acc += w.x * v.x + w.y * v.y + w.z * v.z + w.w * v.w;
        }
        g_gate[(nb * CH + c) * NSEG + ss] = 1.f / (1.f + expf(-acc));
    }
}

// ---------------- kernel 3: gate + dynamic temporal depthwise conv ----------------
// grid: 4096 blocks = (nb, c); 256 threads, float4 per thread over hw
__global__ __launch_bounds__(256) void k_main(const float* __restrict__ x,
                                              float* __restrict__ out) {
    int b  = blockIdx.x;
    int nb = b >> 9, c = b & 511;
    int t  = threadIdx.x;
    const float* gp = g_gate + (nb * CH + c) * NSEG;
    const float* kp = g_gk + (nb * CH + c) * 3;
    float gv[8];
#pragma unroll
    for (int s = 0; s < 8; s++) gv[s] = __ldg(&gp[s]);
    float k0 = __ldg(&kp[0]), k1 = __ldg(&kp[1]), k2 = __ldg(&kp[2]);

    size_t base = (((size_t)nb * NSEG * CH + c) << 10) + ((size_t)t << 2);
    const size_t seg_stride = (size_t)CH << 10;  // 512*1024 floats

    float4 gx[8];
#pragma unroll
    for (int s = 0; s < 8; s++) {
        float4 v = __ldcs((const float4*)(x + base + (size_t)s * seg_stride));
        gx[s].x = v.x * gv[s];
        gx[s].y = v.y * gv[s];
        gx[s].z = v.z * gv[s];
        gx[s].w = v.w * gv[s];
    }
#pragma unroll
    for (int s = 0; s < 8; s++) {
        float4 a;
        a.x = k1 * gx[s].x; a.y = k1 * gx[s].y;
        a.z = k1 * gx[s].z; a.w = k1 * gx[s].w;
        if (s > 0) {
            a.x += k0 * gx[s - 1].x; a.y += k0 * gx[s - 1].y;
            a.z += k0 * gx[s - 1].z; a.w += k0 * gx[s - 1].w;
        }
        if (s < 7) {
            a.x += k2 * gx[s + 1].x; a.y += k2 * gx[s + 1].y;
            a.z += k2 * gx[s + 1].z; a.w += k2 * gx[s + 1].w;
        }
        __stcs((float4*)(out + base + (size_t)s * seg_stride), a);
    }
}

// ---------------- launch ----------------
extern "C" void kernel_launch(void* const* d_in, const int* in_sizes, int n_in,
                              void* d_out, int out_size) {
    const float* x          = (const float*)d_in[0];
    const float* g_w1       = (const float*)d_in[1];
    const float* g_bn_gamma = (const float*)d_in[2];
    const float* g_bn_beta  = (const float*)d_in[3];
    const float* g_bn_mean  = (const float*)d_in[4];
    const float* g_bn_var   = (const float*)d_in[5];
    const float* g_w2       = (const float*)d_in[6];
    const float* l_w1       = (const float*)d_in[7];
    const float* l_bn_gamma = (const float*)d_in[8];
    const float* l_bn_beta  = (const float*)d_in[9];
    const float* l_bn_mean  = (const float*)d_in[10];
    const float* l_bn_var   = (const float*)d_in[11];
    const float* l_w2       = (const float*)d_in[12];
    float* out = (float*)d_out;

    k_theta<<<4096, 256>>>(x);
    k_branch<<<8, 1024>>>(l_w1, g_w1, g_bn_gamma, g_bn_beta, g_bn_mean,
                          g_bn_var, g_w2, l_bn_gamma, l_bn_beta, l_bn_mean,
                          l_bn_var, l_w2);
    k_main<<<4096, 256>>>(x, out);
}

// round 4
// speedup vs baseline: 1.9100x; 1.9100x over previous
#include <cuda_runtime.h>
#include <math.h>

#define NBATCH 8
#define NSEG 8
#define CH 512
#define CBOT 128
#define BN_EPS 1e-5f

// ---------------- scratch (no allocations allowed) ----------------
__device__ float g_theta[NBATCH * CH * NSEG];   // [nb][c][s]
__device__ float g_u    [NBATCH * NSEG * CBOT]; // [nb][s][cb]  (post BN+relu)

// ---------------- kernel 1: theta = spatial mean ----------------
// one warp per (n, c); n = nb*8 + s
__global__ __launch_bounds__(256) void k_theta(const float* __restrict__ x) {
    int wid  = (blockIdx.x * blockDim.x + threadIdx.x) >> 5;
    int lane = threadIdx.x & 31;
    if (wid >= NBATCH * NSEG * CH) return;
    int n = wid >> 9;
    int c = wid & 511;
    const float4* p = (const float4*)(x + (((size_t)n * CH + c) << 10));
    float s = 0.f;
#pragma unroll
    for (int i = 0; i < 8; i++) {
        float4 v = __ldcs(p + lane + (i << 5));
        s += (v.x + v.y) + (v.z + v.w);
    }
#pragma unroll
    for (int o = 16; o; o >>= 1) s += __shfl_xor_sync(0xffffffffu, s, o);
    if (lane == 0) {
        int nb = n >> 3, seg = n & 7;
        g_theta[(nb * CH + c) * NSEG + seg] = s * (1.f / 1024.f);
    }
}

// ---------------- kernel 2: L-branch conv1 + BN + relu -> u ----------------
// grid: 128 blocks = (nb, group of 8 cb); 256 threads = (cbl, s, p)
// p in 0..3 splits the 512-channel sum into 4 partials, shuffle-reduced.
__global__ __launch_bounds__(256) void k_lconv(
        const float* __restrict__ l_w1,
        const float* __restrict__ l_bn_gamma,
        const float* __restrict__ l_bn_beta,
        const float* __restrict__ l_bn_mean,
        const float* __restrict__ l_bn_var) {
    // th[r][c]: r = segment+1 (rows 0 and 9 zero pad). stride 520 floats
    __shared__ __align__(16) float th[10][520];

    int nb  = blockIdx.x >> 4;
    int grp = blockIdx.x & 15;
    int t   = threadIdx.x;

    // stage theta[nb]: 512 channels x 8 segments (coalesced over c)
#pragma unroll
    for (int j = 0; j < 16; j++) {
        int o = j * 256 + t;
        int c = o >> 3, s = o & 7;
        th[s + 1][c] = g_theta[(nb * CH + c) * NSEG + s];
    }
    for (int o = t; o < 520; o += 256) { th[0][o] = 0.f; th[9][o] = 0.f; }
    __syncthreads();

    int cbl = t >> 5;           // 0..7
    int s   = (t >> 2) & 7;     // 0..7
    int p   = t & 3;            // 0..3
    int cb  = grp * 8 + cbl;

    const float4* wp = (const float4*)(l_w1 + (size_t)cb * (CH * 3) + (size_t)p * 384);
    const float* rm = &th[s    ][p * 128];  // segment s-1
    const float* r0 = &th[s + 1][p * 128];  // segment s
    const float* rp = &th[s + 2][p * 128];  // segment s+1

    float acc = 0.f;
#pragma unroll 8
    for (int q = 0; q < 32; q++) {  // 4 channels per iter, 128 per partial
        float4 wa = wp[3 * q + 0];
        float4 wb = wp[3 * q + 1];
        float4 wc = wp[3 * q + 2];
        float4 tm = *(const float4*)(rm + 4 * q);
        float4 t0 = *(const float4*)(r0 + 4 * q);
        float4 tp = *(const float4*)(rp + 4 * q);
        acc += wa.x * tm.x + wa.y * t0.x + wa.z * tp.x;
        acc += wa.w * tm.y + wb.x * t0.y + wb.y * tp.y;
        acc += wb.z * tm.z + wb.w * t0.z + wc.x * tp.z;
        acc += wc.y * tm.w + wc.z * t0.w + wc.w * tp.w;
    }
    // reduce the 4 channel-partials (lanes differing in bits 0..1)
    acc += __shfl_xor_sync(0xffffffffu, acc, 1);
    acc += __shfl_xor_sync(0xffffffffu, acc, 2);

    if (p == 0) {
        acc = (acc - __ldg(&l_bn_mean[cb])) *
              rsqrtf(__ldg(&l_bn_var[cb]) + BN_EPS) * __ldg(&l_bn_gamma[cb]) +
              __ldg(&l_bn_beta[cb]);
        g_u[(nb * NSEG + s) * CBOT + cb] = fmaxf(acc, 0.f);
    }
}

// ---------------- kernel 3: gate + softmax-kernel prologue, then
//                  gated dynamic temporal depthwise conv ----------------
// grid: 4096 blocks = (nb, c); 256 threads, float4 per thread over hw
__global__ __launch_bounds__(256) void k_main(
        const float* __restrict__ x, float* __restrict__ out,
        const float* __restrict__ g_w1,
        const float* __restrict__ g_bn_gamma,
        const float* __restrict__ g_bn_beta,
        const float* __restrict__ g_bn_mean,
        const float* __restrict__ g_bn_var,
        const float* __restrict__ g_w2,
        const float* __restrict__ l_w2) {
    __shared__ float sm_a[16];
    __shared__ float sm_k[3];
    __shared__ float sm_gate[8];

    int b  = blockIdx.x;
    int nb = b >> 9, c = b & 511;
    int t  = threadIdx.x;
    int w  = t >> 5, lane = t & 31;

    // ---- gate[s=w]: dot(u[nb][s][:], l_w2[c][:]) over 128 cb ----
    {
        float4 uv = *(const float4*)(g_u + ((size_t)(nb * NSEG + w) * CBOT) + 4 * lane);
        float4 wv = __ldg((const float4*)(l_w2 + (size_t)c * CBOT + 4 * lane));
        float pr = uv.x * wv.x + uv.y * wv.y + uv.z * wv.z + uv.w * wv.w;
#pragma unroll
        for (int o = 16; o; o >>= 1) pr += __shfl_xor_sync(0xffffffffu, pr, o);
        if (lane == 0) sm_gate[w] = 1.f / (1.f + expf(-pr));
    }

    // ---- G-branch hidden layer: threads 0..15 ----
    const float* thp = g_theta + ((size_t)(nb * CH + c)) * NSEG;
    if (t < 16) {
        float a = 0.f;
#pragma unroll
        for (int s = 0; s < 8; s++) a += __ldg(&g_w1[t * 8 + s]) * __ldg(&thp[s]);
        a = (a - __ldg(&g_bn_mean[t])) *
            rsqrtf(__ldg(&g_bn_var[t]) + BN_EPS) * __ldg(&g_bn_gamma[t]) +
            __ldg(&g_bn_beta[t]);
        sm_a[t] = fmaxf(a, 0.f);
    }
    __syncthreads();

    if (t == 0) {
        float tk0 = 0.f, tk1 = 0.f, tk2 = 0.f;
#pragma unroll
        for (int i = 0; i < 16; i++) {
            float a = sm_a[i];
            tk0 += __ldg(&g_w2[0 * 16 + i]) * a;
            tk1 += __ldg(&g_w2[1 * 16 + i]) * a;
            tk2 += __ldg(&g_w2[2 * 16 + i]) * a;
        }
        float m  = fmaxf(tk0, fmaxf(tk1, tk2));
        float e0 = expf(tk0 - m), e1 = expf(tk1 - m), e2 = expf(tk2 - m);
        float inv = 1.f / (e0 + e1 + e2);
        sm_k[0] = e0 * inv; sm_k[1] = e1 * inv; sm_k[2] = e2 * inv;
    }
    __syncthreads();

    float gv[8];
#pragma unroll
    for (int s = 0; s < 8; s++) gv[s] = sm_gate[s];
    float k0 = sm_k[0], k1 = sm_k[1], k2 = sm_k[2];

    // ---- streaming main loop ----
    size_t base = (((size_t)nb * NSEG * CH + c) << 10) + ((size_t)t << 2);
    const size_t seg_stride = (size_t)CH << 10;  // 512*1024 floats

    float4 gx[8];
#pragma unroll
    for (int s = 0; s < 8; s++) {
        float4 v = __ldcs((const float4*)(x + base + (size_t)s * seg_stride));
        gx[s].x = v.x * gv[s];
        gx[s].y = v.y * gv[s];
        gx[s].z = v.z * gv[s];
        gx[s].w = v.w * gv[s];
    }
#pragma unroll
    for (int s = 0; s < 8; s++) {
        float4 a;
        a.x = k1 * gx[s].x; a.y = k1 * gx[s].y;
        a.z = k1 * gx[s].z; a.w = k1 * gx[s].w;
        if (s > 0) {
            a.x += k0 * gx[s - 1].x; a.y += k0 * gx[s - 1].y;
            a.z += k0 * gx[s - 1].z; a.w += k0 * gx[s - 1].w;
        }
        if (s < 7) {
            a.x += k2 * gx[s + 1].x; a.y += k2 * gx[s + 1].y;
            a.z += k2 * gx[s + 1].z; a.w += k2 * gx[s + 1].w;
        }
        __stcs((float4*)(out + base + (size_t)s * seg_stride), a);
    }
}

// ---------------- launch ----------------
extern "C" void kernel_launch(void* const* d_in, const int* in_sizes, int n_in,
                              void* d_out, int out_size) {
    const float* x          = (const float*)d_in[0];
    const float* g_w1       = (const float*)d_in[1];
    const float* g_bn_gamma = (const float*)d_in[2];
    const float* g_bn_beta  = (const float*)d_in[3];
    const float* g_bn_mean  = (const float*)d_in[4];
    const float* g_bn_var   = (const float*)d_in[5];
    const float* g_w2       = (const float*)d_in[6];
    const float* l_w1       = (const float*)d_in[7];
    const float* l_bn_gamma = (const float*)d_in[8];
    const float* l_bn_beta  = (const float*)d_in[9];
    const float* l_bn_mean  = (const float*)d_in[10];
    const float* l_bn_var   = (const float*)d_in[11];
    const float* l_w2       = (const float*)d_in[12];
    float* out = (float*)d_out;

    k_theta<<<4096, 256>>>(x);
    k_lconv<<<128, 256>>>(l_w1, l_bn_gamma, l_bn_beta, l_bn_mean, l_bn_var);
    k_main<<<4096, 256>>>(x, out, g_w1, g_bn_gamma, g_bn_beta,
                          g_bn_mean, g_bn_var, g_w2, l_w2);
}

// round 7
// speedup vs baseline: 2.0016x; 1.0480x over previous
#include <cuda_runtime.h>
#include <math.h>

#define NBATCH 8
#define NSEG 8
#define CH 512
#define CBOT 128
#define BN_EPS 1e-5f

// ---------------- scratch (no allocations allowed) ----------------
__device__ float g_theta[NBATCH * CH * NSEG];   // [nb][c][s]
__device__ float g_u    [NBATCH * NSEG * CBOT]; // [nb][s][cb]  (post BN+relu)

// ---------------- kernel 1: theta = spatial mean ----------------
// one warp per (n, c); n = nb*8 + s
// NOTE: default cache policy (NOT __ldcs) so x populates L2 for k_main's
// reverse-order re-read one launch later.
__global__ __launch_bounds__(256) void k_theta(const float* __restrict__ x) {
    int wid  = (blockIdx.x * blockDim.x + threadIdx.x) >> 5;
    int lane = threadIdx.x & 31;
    if (wid >= NBATCH * NSEG * CH) return;
    int n = wid >> 9;
    int c = wid & 511;
    const float4* p = (const float4*)(x + (((size_t)n * CH + c) << 10));
    float s = 0.f;
#pragma unroll
    for (int i = 0; i < 8; i++) {
        float4 v = p[lane + (i << 5)];
        s += (v.x + v.y) + (v.z + v.w);
    }
#pragma unroll
    for (int o = 16; o; o >>= 1) s += __shfl_xor_sync(0xffffffffu, s, o);
    if (lane == 0) {
        int nb = n >> 3, seg = n & 7;
        g_theta[(nb * CH + c) * NSEG + seg] = s * (1.f / 1024.f);
    }
}

// ---------------- kernel 2: L-branch conv1 + BN + relu -> u ----------------
// grid: 128 blocks = (nb, group of 8 cb); 256 threads = (cbl, s, p)
// p in 0..3 splits the 512-channel sum into 4 partials, shuffle-reduced.
__global__ __launch_bounds__(256) void k_lconv(
        const float* __restrict__ l_w1,
        const float* __restrict__ l_bn_gamma,
        const float* __restrict__ l_bn_beta,
        const float* __restrict__ l_bn_mean,
        const float* __restrict__ l_bn_var) {
    // th[r][c]: r = segment+1 (rows 0 and 9 zero pad). stride 520 floats
    __shared__ __align__(16) float th[10][520];

    int nb  = blockIdx.x >> 4;
    int grp = blockIdx.x & 15;
    int t   = threadIdx.x;

    // stage theta[nb]: 512 channels x 8 segments (coalesced over c)
#pragma unroll
    for (int j = 0; j < 16; j++) {
        int o = j * 256 + t;
        int c = o >> 3, s = o & 7;
        th[s + 1][c] = g_theta[(nb * CH + c) * NSEG + s];
    }
    for (int o = t; o < 520; o += 256) { th[0][o] = 0.f; th[9][o] = 0.f; }
    __syncthreads();

    int cbl = t >> 5;           // 0..7
    int s   = (t >> 2) & 7;     // 0..7
    int p   = t & 3;            // 0..3
    int cb  = grp * 8 + cbl;

    const float4* wp = (const float4*)(l_w1 + (size_t)cb * (CH * 3) + (size_t)p * 384);
    const float* rm = &th[s    ][p * 128];  // segment s-1
    const float* r0 = &th[s + 1][p * 128];  // segment s
    const float* rp = &th[s + 2][p * 128];  // segment s+1

    float acc = 0.f;
#pragma unroll 8
    for (int q = 0; q < 32; q++) {  // 4 channels per iter, 128 per partial
        float4 wa = wp[3 * q + 0];
        float4 wb = wp[3 * q + 1];
        float4 wc = wp[3 * q + 2];
        float4 tm = *(const float4*)(rm + 4 * q);
        float4 t0 = *(const float4*)(r0 + 4 * q);
        float4 tp = *(const float4*)(rp + 4 * q);
        acc += wa.x * tm.x + wa.y * t0.x + wa.z * tp.x;
        acc += wa.w * tm.y + wb.x * t0.y + wb.y * tp.y;
        acc += wb.z * tm.z + wb.w * t0.z + wc.x * tp.z;
        acc += wc.y * tm.w + wc.z * t0.w + wc.w * tp.w;
    }
    // reduce the 4 channel-partials (lanes differing in bits 0..1)
    acc += __shfl_xor_sync(0xffffffffu, acc, 1);
    acc += __shfl_xor_sync(0xffffffffu, acc, 2);

    if (p == 0) {
        acc = (acc - __ldg(&l_bn_mean[cb])) *
              rsqrtf(__ldg(&l_bn_var[cb]) + BN_EPS) * __ldg(&l_bn_gamma[cb]) +
              __ldg(&l_bn_beta[cb]);
        g_u[(nb * NSEG + s) * CBOT + cb] = fmaxf(acc, 0.f);
    }
}

// ---------------- kernel 3: gate + softmax-kernel prologue, then
//                  gated dynamic temporal depthwise conv ----------------
// grid: 4096 blocks; REVERSE bid order so the sweep starts at the tail of x,
// which is the L2-resident portion left by k_theta's forward fill.
__global__ __launch_bounds__(256) void k_main(
        const float* __restrict__ x, float* __restrict__ out,
        const float* __restrict__ g_w1,
        const float* __restrict__ g_bn_gamma,
        const float* __restrict__ g_bn_beta,
        const float* __restrict__ g_bn_mean,
        const float* __restrict__ g_bn_var,
        const float* __restrict__ g_w2,
        const float* __restrict__ l_w2) {
    __shared__ float sm_a[16];
    __shared__ float sm_k[3];
    __shared__ float sm_gate[8];

    int b  = 4095 - blockIdx.x;      // reverse sweep
    int nb = b >> 9, c = b & 511;
    int t  = threadIdx.x;
    int w  = t >> 5, lane = t & 31;

    // ---- gate[s=w]: dot(u[nb][s][:], l_w2[c][:]) over 128 cb ----
    {
        float4 uv = *(const float4*)(g_u + ((size_t)(nb * NSEG + w) * CBOT) + 4 * lane);
        float4 wv = __ldg((const float4*)(l_w2 + (size_t)c * CBOT + 4 * lane));
        float pr = uv.x * wv.x + uv.y * wv.y + uv.z * wv.z + uv.w * wv.w;
#pragma unroll
        for (int o = 16; o; o >>= 1) pr += __shfl_xor_sync(0xffffffffu, pr, o);
        if (lane == 0) sm_gate[w] = 1.f / (1.f + expf(-pr));
    }

    // ---- G-branch hidden layer: threads 0..15 ----
    const float* thp = g_theta + ((size_t)(nb * CH + c)) * NSEG;
    if (t < 16) {
        float a = 0.f;
#pragma unroll
        for (int s = 0; s < 8; s++) a += __ldg(&g_w1[t * 8 + s]) * __ldg(&thp[s]);
        a = (a - __ldg(&g_bn_mean[t])) *
            rsqrtf(__ldg(&g_bn_var[t]) + BN_EPS) * __ldg(&g_bn_gamma[t]) +
            __ldg(&g_bn_beta[t]);
        sm_a[t] = fmaxf(a, 0.f);
    }
    __syncthreads();

    if (t == 0) {
        float tk0 = 0.f, tk1 = 0.f, tk2 = 0.f;
#pragma unroll
        for (int i = 0; i < 16; i++) {
            float a = sm_a[i];
            tk0 += __ldg(&g_w2[0 * 16 + i]) * a;
            tk1 += __ldg(&g_w2[1 * 16 + i]) * a;
            tk2 += __ldg(&g_w2[2 * 16 + i]) * a;
        }
        float m  = fmaxf(tk0, fmaxf(tk1, tk2));
        float e0 = expf(tk0 - m), e1 = expf(tk1 - m), e2 = expf(tk2 - m);
        float inv = 1.f / (e0 + e1 + e2);
        sm_k[0] = e0 * inv; sm_k[1] = e1 * inv; sm_k[2] = e2 * inv;
    }
    __syncthreads();

    float gv[8];
#pragma unroll
    for (int s = 0; s < 8; s++) gv[s] = sm_gate[s];
    float k0 = sm_k[0], k1 = sm_k[1], k2 = sm_k[2];

    // ---- streaming main loop ----
    size_t base = (((size_t)nb * NSEG * CH + c) << 10) + ((size_t)t << 2);
    const size_t seg_stride = (size_t)CH << 10;  // 512*1024 floats

    float4 gx[8];
#pragma unroll
    for (int s = 0; s < 8; s++) {
        float4 v = __ldcs((const float4*)(x + base + (size_t)s * seg_stride));
        gx[s].x = v.x * gv[s];
        gx[s].y = v.y * gv[s];
        gx[s].z = v.z * gv[s];
        gx[s].w = v.w * gv[s];
    }
#pragma unroll
    for (int s = 0; s < 8; s++) {
        float4 a;
        a.x = k1 * gx[s].x; a.y = k1 * gx[s].y;
        a.z = k1 * gx[s].z; a.w = k1 * gx[s].w;
        if (s > 0) {
            a.x += k0 * gx[s - 1].x; a.y += k0 * gx[s - 1].y;
            a.z += k0 * gx[s - 1].z; a.w += k0 * gx[s - 1].w;
        }
        if (s < 7) {
            a.x += k2 * gx[s + 1].x; a.y += k2 * gx[s + 1].y;
            a.z += k2 * gx[s + 1].z; a.w += k2 * gx[s + 1].w;
        }
        __stcs((float4*)(out + base + (size_t)s * seg_stride), a);
    }
}

// ---------------- launch ----------------
extern "C" void kernel_launch(void* const* d_in, const int* in_sizes, int n_in,
                              void* d_out, int out_size) {
    const float* x          = (const float*)d_in[0];
    const float* g_w1       = (const float*)d_in[1];
    const float* g_bn_gamma = (const float*)d_in[2];
    const float* g_bn_beta  = (const float*)d_in[3];
    const float* g_bn_mean  = (const float*)d_in[4];
    const float* g_bn_var   = (const float*)d_in[5];
    const float* g_w2       = (const float*)d_in[6];
    const float* l_w1       = (const float*)d_in[7];
    const float* l_bn_gamma = (const float*)d_in[8];
    const float* l_bn_beta  = (const float*)d_in[9];
    const float* l_bn_mean  = (const float*)d_in[10];
    const float* l_bn_var   = (const float*)d_in[11];
    const float* l_w2       = (const float*)d_in[12];
    float* out = (float*)d_out;

    k_theta<<<4096, 256>>>(x);
    k_lconv<<<128, 256>>>(l_w1, l_bn_gamma, l_bn_beta, l_bn_mean, l_bn_var);
    k_main<<<4096, 256>>>(x, out, g_w1, g_bn_gamma, g_bn_beta,
                          g_bn_mean, g_bn_var, g_w2, l_w2);
}